// round 5
// baseline (speedup 1.0000x reference)
#include <cuda_runtime.h>
#include <cuda_bf16.h>
#include <cstdint>
#include <cstddef>

// Problem constants
#define Vn 100000
#define Kn 64
#define Fn 16
#define VPB 8
#define EPSc 1e-4f
#define NTILES 100000        // 16-row MLP tiles
#define TPB 12               // tiles per block (6 warps x 2)

static const int R_ROWS = Vn * Fn;

// Scratch: cov rows [V*F, 9] (static device allocation — allowed)
__device__ float g_cov[(size_t)Vn * Fn * 9];

// ---------------------------------------------------------------------------
// Warp-MMA helpers (sm_80-era PTX: legal on plain sm_100)
// ---------------------------------------------------------------------------
__device__ __forceinline__ uint32_t smem_u32(const void* p) {
    uint32_t a;
    asm("{ .reg .u64 t; cvta.to.shared.u64 t, %1; cvt.u32.u64 %0, t; }"
        : "=r"(a) : "l"(p));
    return a;
}

__device__ __forceinline__ void mma_bf16(float* d, const uint32_t* a,
                                         uint32_t b0, uint32_t b1) {
    asm volatile(
        "mma.sync.aligned.m16n8k16.row.col.f32.bf16.bf16.f32 "
        "{%0,%1,%2,%3}, {%4,%5,%6,%7}, {%8,%9}, {%0,%1,%2,%3};"
        : "+f"(d[0]), "+f"(d[1]), "+f"(d[2]), "+f"(d[3])
        : "r"(a[0]), "r"(a[1]), "r"(a[2]), "r"(a[3]), "r"(b0), "r"(b1));
}

__device__ __forceinline__ void ldsm4(uint32_t* r, uint32_t addr) {
    asm volatile("ldmatrix.sync.aligned.m8n8.x4.shared.b16 {%0,%1,%2,%3}, [%4];"
                 : "=r"(r[0]), "=r"(r[1]), "=r"(r[2]), "=r"(r[3])
                 : "r"(addr) : "memory");
}

__device__ __forceinline__ void split2(float x0, float x1, uint32_t& h, uint32_t& l) {
    uint32_t hp;
    asm("cvt.rn.bf16x2.f32 %0, %1, %2;" : "=r"(hp) : "f"(x1), "f"(x0));
    const float h0 = __uint_as_float(hp << 16);
    const float h1 = __uint_as_float(hp & 0xFFFF0000u);
    const float l0 = x0 - h0;
    const float l1 = x1 - h1;
    uint32_t lp;
    asm("cvt.rn.bf16x2.f32 %0, %1, %2;" : "=r"(lp) : "f"(l1), "f"(l0));
    h = hp; l = lp;
}

__device__ __forceinline__ float elu_fast(float x) {
    return x > 0.f ? x : (__expf(x) - 1.0f);
}

// ---------------------------------------------------------------------------
// Kernel A: weighted neighbour covariance (unchanged)
// ---------------------------------------------------------------------------
__global__ void __launch_bounds__(128) cov_kernel(
    const float* __restrict__ coords,
    const float* __restrict__ distsq,
    const float* __restrict__ feats,
    const int*   __restrict__ nidx)
{
    __shared__ int   s_idx[VPB * Kn];
    __shared__ float s_ex [VPB * Kn];
    __shared__ float s_nbc[VPB * Kn * 3];

    const int v0 = blockIdx.x * VPB;

    for (int p = threadIdx.x; p < VPB * Kn; p += 128) {
        const int v  = v0 + (p >> 6);
        const int kk = p & 63;
        const int idx = nidx[v * Kn + kk];
        s_idx[p] = idx;
        s_ex[p]  = __expf(-10.0f * distsq[v * Kn + kk]);
        s_nbc[p * 3 + 0] = coords[idx * 3 + 0];
        s_nbc[p * 3 + 1] = coords[idx * 3 + 1];
        s_nbc[p * 3 + 2] = coords[idx * 3 + 2];
    }
    __syncthreads();

    const int lv = threadIdx.x >> 4;
    const int f  = threadIdx.x & 15;
    const int base = lv * Kn;

    float ws = 0.f, m0 = 0.f, m1 = 0.f, m2 = 0.f;
    float q00 = 0.f, q01 = 0.f, q02 = 0.f, q11 = 0.f, q12 = 0.f, q22 = 0.f;

    #pragma unroll 4
    for (int kk = 0; kk < Kn; kk++) {
        const int idx = s_idx[base + kk];
        const float w = __ldg(&feats[idx * Fn + f]) * s_ex[base + kk];
        const float x = s_nbc[(base + kk) * 3 + 0];
        const float y = s_nbc[(base + kk) * 3 + 1];
        const float z = s_nbc[(base + kk) * 3 + 2];
        ws += w;
        m0 = fmaf(w, x, m0); m1 = fmaf(w, y, m1); m2 = fmaf(w, z, m2);
        const float wx = w * x, wy = w * y, wz = w * z;
        q00 = fmaf(wx, x, q00); q01 = fmaf(wx, y, q01); q02 = fmaf(wx, z, q02);
        q11 = fmaf(wy, y, q11); q12 = fmaf(wy, z, q12); q22 = fmaf(wz, z, q22);
    }

    const float inv = 1.0f / (ws + EPSc);
    const float mu0 = m0 * inv, mu1 = m1 * inv, mu2 = m2 * inv;
    const float c0 = q00 * inv - mu0 * mu0;
    const float c1 = q01 * inv - mu0 * mu1;
    const float c2 = q02 * inv - mu0 * mu2;
    const float c4 = q11 * inv - mu1 * mu1;
    const float c5 = q12 * inv - mu1 * mu2;
    const float c8 = q22 * inv - mu2 * mu2;

    float* o = g_cov + ((size_t)(v0 + lv) * Fn + f) * 9;
    o[0] = c0; o[1] = c1; o[2] = c2;
    o[3] = c1; o[4] = c4; o[5] = c5;
    o[6] = c2; o[7] = c5; o[8] = c8;
}

// ---------------------------------------------------------------------------
// Kernel B v5: warp-MMA bf16-split MLP, TWO 16-row tiles per warp.
// Every weight-fragment ldmatrix feeds 12 MMAs (was 6) -> B LDSM per tile halved.
// ---------------------------------------------------------------------------
#define PB   72
#define PB0  24
#define OFF_B1H 0
#define OFF_B1L 9216
#define OFF_B2H 18432
#define OFF_B2L 27648
#define OFF_B0H 36864
#define OFF_B0L 39936
#define OFF_B3H 43008
#define OFF_B3L 45312
#define OFF_BIAS 47616          /* 208 floats */
#define OFF_AH  48448           /* 12 tiles x 512 B */
#define OFF_AL  54592
#define MLP_SMEM 60736

__device__ __forceinline__ void put_hl(char* smc, int offH, int offL, int idx, float v) {
    const __nv_bfloat16 hb = __float2bfloat16_rn(v);
    const float lo = v - __bfloat162float(hb);
    ((__nv_bfloat16*)(smc + offH))[idx] = hb;
    ((__nv_bfloat16*)(smc + offL))[idx] = __float2bfloat16_rn(lo);
}

// Hidden layer for two tiles: d0/d1 += (A0,A1) x B(hi/lo), K=64, N=64.
__device__ __forceinline__ void hidden_layer2(
    float* d0, float* d1,
    const uint32_t* AH0, const uint32_t* AL0,
    const uint32_t* AH1, const uint32_t* AL1,
    uint32_t sb, int offH, int offL, int n, int koff)
{
    #pragma unroll
    for (int s = 0; s < 4; s++) {
        const uint32_t* ah0 = AH0 + 4 * s;
        const uint32_t* al0 = AL0 + 4 * s;
        const uint32_t* ah1 = AH1 + 4 * s;
        const uint32_t* al1 = AL1 + 4 * s;
        #pragma unroll
        for (int ntp = 0; ntp < 4; ntp++) {
            const uint32_t ba = sb + ((n + ntp * 16) * PB + 16 * s + koff) * 2;
            uint32_t bh[4], bl[4];
            ldsm4(bh, ba + offH);
            ldsm4(bl, ba + offL);
            float* p0 = d0 + ntp * 8;
            float* p1 = d1 + ntp * 8;
            mma_bf16(p0, ah0, bh[0], bh[1]);
            mma_bf16(p1, ah1, bh[0], bh[1]);
            mma_bf16(p0, ah0, bl[0], bl[1]);
            mma_bf16(p1, ah1, bl[0], bl[1]);
            mma_bf16(p0, al0, bh[0], bh[1]);
            mma_bf16(p1, al1, bh[0], bh[1]);
            mma_bf16(p0 + 4, ah0, bh[2], bh[3]);
            mma_bf16(p1 + 4, ah1, bh[2], bh[3]);
            mma_bf16(p0 + 4, ah0, bl[2], bl[3]);
            mma_bf16(p1 + 4, ah1, bl[2], bl[3]);
            mma_bf16(p0 + 4, al0, bh[2], bh[3]);
            mma_bf16(p1 + 4, al1, bh[2], bh[3]);
        }
    }
}

// Epilogue: bias + ELU on d[32] (64 cols), repack into next-layer A frags.
__device__ __forceinline__ void epi_repack(
    float* d, const float* bias, uint32_t* AH, uint32_t* AL, int lane)
{
    const int c = (lane & 3) * 2;
    #pragma unroll
    for (int t = 0; t < 8; t++) {
        const float bc0 = bias[8 * t + c];
        const float bc1 = bias[8 * t + c + 1];
        d[4 * t + 0] = elu_fast(d[4 * t + 0] + bc0);
        d[4 * t + 1] = elu_fast(d[4 * t + 1] + bc1);
        d[4 * t + 2] = elu_fast(d[4 * t + 2] + bc0);
        d[4 * t + 3] = elu_fast(d[4 * t + 3] + bc1);
    }
    #pragma unroll
    for (int s = 0; s < 4; s++) {
        split2(d[8 * s + 0], d[8 * s + 1], AH[4 * s + 0], AL[4 * s + 0]);
        split2(d[8 * s + 2], d[8 * s + 3], AH[4 * s + 1], AL[4 * s + 1]);
        split2(d[8 * s + 4], d[8 * s + 5], AH[4 * s + 2], AL[4 * s + 2]);
        split2(d[8 * s + 6], d[8 * s + 7], AH[4 * s + 3], AL[4 * s + 3]);
    }
}

__global__ void __launch_bounds__(192, 2) mlp_kernel(
    const float* __restrict__ W0, const float* __restrict__ b0,
    const float* __restrict__ W1, const float* __restrict__ b1,
    const float* __restrict__ W2, const float* __restrict__ b2,
    const float* __restrict__ W3, const float* __restrict__ b3,
    float* __restrict__ out)
{
    extern __shared__ char smc[];
    const uint32_t sb = smem_u32(smc);
    const int tid = threadIdx.x;
    const int lane = tid & 31;
    const int wid = tid >> 5;            // 0..5
    float* bias = (float*)(smc + OFF_BIAS);

    // ---- Stage weights (transposed, hi/lo split) + biases ----
    for (int i = tid; i < 4096; i += 192) {
        const int n = i & 63, k = i >> 6;
        put_hl(smc, OFF_B1H, OFF_B1L, n * PB + k, W1[k * 64 + n]);
        put_hl(smc, OFF_B2H, OFF_B2L, n * PB + k, W2[k * 64 + n]);
    }
    for (int i = tid; i < 1024; i += 192) {
        const int n0 = i >> 4, k0 = i & 15;
        put_hl(smc, OFF_B0H, OFF_B0L, n0 * PB0 + k0, (k0 < 9) ? W0[k0 * 64 + n0] : 0.f);
        const int n3 = i >> 6, k3 = i & 63;
        put_hl(smc, OFF_B3H, OFF_B3L, n3 * PB + k3, (n3 < 9) ? W3[k3 * 9 + n3] : 0.f);
    }
    for (int i = tid; i < 208; i += 192) {
        float v = 0.f;
        if (i < 64) v = b0[i];
        else if (i < 128) v = b1[i - 64];
        else if (i < 192) v = b2[i - 128];
        else if (i < 201) v = b3[i - 192];
        bias[i] = v;
    }
    __syncthreads();

    // ---- Two tiles per warp ----
    const int base = blockIdx.x * TPB + wid * 2;  // tile0 = base, tile1 = base+1

    // Stage input: 32 rows (16 per tile); lanes 0-15 -> tile0, 16-31 -> tile1
    {
        const int t_ln = lane >> 4;
        const int tile_ln = base + t_ln;
        uint32_t* ph = (uint32_t*)(smc + OFF_AH + wid * 1024 + (lane & 15) * 32 + t_ln * 512);
        uint32_t* pl = (uint32_t*)(smc + OFF_AL + wid * 1024 + (lane & 15) * 32 + t_ln * 512);
        if (tile_ln < NTILES) {
            const float* src = g_cov + ((size_t)tile_ln * 16 + (lane & 15)) * 9;
            float x[10];
            #pragma unroll
            for (int q = 0; q < 9; q++) x[q] = src[q];
            x[9] = 0.f;
            #pragma unroll
            for (int cq = 0; cq < 5; cq++) {
                uint32_t h, l;
                split2(x[2 * cq], x[2 * cq + 1], h, l);
                ph[cq] = h; pl[cq] = l;
            }
            #pragma unroll
            for (int cq = 5; cq < 8; cq++) { ph[cq] = 0u; pl[cq] = 0u; }
        } else {
            #pragma unroll
            for (int cq = 0; cq < 8; cq++) { ph[cq] = 0u; pl[cq] = 0u; }
        }
    }
    __syncwarp();

    uint32_t A0h[2][4], A0l[2][4];
    #pragma unroll
    for (int t = 0; t < 2; t++) {
        const uint32_t aaddr = sb + OFF_AH + wid * 1024 + t * 512
                             + (lane & 15) * 32 + ((lane >> 4) << 4);
        ldsm4(A0h[t], aaddr);
        ldsm4(A0l[t], aaddr + (OFF_AL - OFF_AH));
    }

    const int n    = (lane & 7) + ((lane >> 4) << 3);
    const int koff = ((lane >> 3) & 1) * 8;

    float d0[32], d1[32];
    #pragma unroll
    for (int j = 0; j < 32; j++) { d0[j] = 0.f; d1[j] = 0.f; }

    // ---- Layer 0: K=16 (9 real), N=64, both tiles ----
    #pragma unroll
    for (int ntp = 0; ntp < 4; ntp++) {
        const uint32_t ba = sb + ((n + ntp * 16) * PB0 + koff) * 2;
        uint32_t bh[4], bl[4];
        ldsm4(bh, ba + OFF_B0H);
        ldsm4(bl, ba + OFF_B0L);
        float* p0 = d0 + ntp * 8;
        float* p1 = d1 + ntp * 8;
        mma_bf16(p0, A0h[0], bh[0], bh[1]);
        mma_bf16(p1, A0h[1], bh[0], bh[1]);
        mma_bf16(p0, A0h[0], bl[0], bl[1]);
        mma_bf16(p1, A0h[1], bl[0], bl[1]);
        mma_bf16(p0, A0l[0], bh[0], bh[1]);
        mma_bf16(p1, A0l[1], bh[0], bh[1]);
        mma_bf16(p0 + 4, A0h[0], bh[2], bh[3]);
        mma_bf16(p1 + 4, A0h[1], bh[2], bh[3]);
        mma_bf16(p0 + 4, A0h[0], bl[2], bl[3]);
        mma_bf16(p1 + 4, A0h[1], bl[2], bl[3]);
        mma_bf16(p0 + 4, A0l[0], bh[2], bh[3]);
        mma_bf16(p1 + 4, A0l[1], bh[2], bh[3]);
    }

    uint32_t AH0[16], AL0[16], AH1[16], AL1[16];

    // ---- Layer 1 ----
    epi_repack(d0, bias + 0, AH0, AL0, lane);
    epi_repack(d1, bias + 0, AH1, AL1, lane);
    #pragma unroll
    for (int j = 0; j < 32; j++) { d0[j] = 0.f; d1[j] = 0.f; }
    hidden_layer2(d0, d1, AH0, AL0, AH1, AL1, sb, OFF_B1H, OFF_B1L, n, koff);

    // ---- Layer 2 ----
    epi_repack(d0, bias + 64, AH0, AL0, lane);
    epi_repack(d1, bias + 64, AH1, AL1, lane);
    #pragma unroll
    for (int j = 0; j < 32; j++) { d0[j] = 0.f; d1[j] = 0.f; }
    hidden_layer2(d0, d1, AH0, AL0, AH1, AL1, sb, OFF_B2H, OFF_B2L, n, koff);

    // ---- Layer 3: K=64, N=16 (9 real) ----
    epi_repack(d0, bias + 128, AH0, AL0, lane);
    epi_repack(d1, bias + 128, AH1, AL1, lane);

    float e0[8], e1[8];
    #pragma unroll
    for (int j = 0; j < 8; j++) { e0[j] = 0.f; e1[j] = 0.f; }
    #pragma unroll
    for (int s = 0; s < 4; s++) {
        const uint32_t ba = sb + (n * PB + 16 * s + koff) * 2;
        uint32_t bh[4], bl[4];
        ldsm4(bh, ba + OFF_B3H);
        ldsm4(bl, ba + OFF_B3L);
        mma_bf16(e0, AH0 + 4 * s, bh[0], bh[1]);
        mma_bf16(e1, AH1 + 4 * s, bh[0], bh[1]);
        mma_bf16(e0, AH0 + 4 * s, bl[0], bl[1]);
        mma_bf16(e1, AH1 + 4 * s, bl[0], bl[1]);
        mma_bf16(e0, AL0 + 4 * s, bh[0], bh[1]);
        mma_bf16(e1, AL1 + 4 * s, bh[0], bh[1]);
        mma_bf16(e0 + 4, AH0 + 4 * s, bh[2], bh[3]);
        mma_bf16(e1 + 4, AH1 + 4 * s, bh[2], bh[3]);
        mma_bf16(e0 + 4, AH0 + 4 * s, bl[2], bl[3]);
        mma_bf16(e1 + 4, AH1 + 4 * s, bl[2], bl[3]);
        mma_bf16(e0 + 4, AL0 + 4 * s, bh[2], bh[3]);
        mma_bf16(e1 + 4, AL1 + 4 * s, bh[2], bh[3]);
    }

    // ---- Final bias + accurate ELU + store (both tiles) ----
    const int row = lane >> 2;
    const int c0  = (lane & 3) * 2;
    const float bc0 = bias[192 + c0];
    const float bc1 = bias[192 + c0 + 1];
    const float b8  = bias[200];
    #pragma unroll
    for (int t = 0; t < 2; t++) {
        const int tile = base + t;
        if (tile >= NTILES) break;
        const float* e = t ? e1 : e0;
        float* o0 = out + ((size_t)tile * 16 + row) * 9;
        float* o1 = o0 + 8 * 9;
        float v;
        v = e[0] + bc0; o0[c0]     = v > 0.f ? v : expm1f(v);
        v = e[1] + bc1; o0[c0 + 1] = v > 0.f ? v : expm1f(v);
        v = e[2] + bc0; o1[c0]     = v > 0.f ? v : expm1f(v);
        v = e[3] + bc1; o1[c0 + 1] = v > 0.f ? v : expm1f(v);
        if ((lane & 3) == 0) {
            v = e[4] + b8; o0[8] = v > 0.f ? v : expm1f(v);
            v = e[6] + b8; o1[8] = v > 0.f ? v : expm1f(v);
        }
    }
}

// ---------------------------------------------------------------------------
// Launch
// ---------------------------------------------------------------------------
extern "C" void kernel_launch(void* const* d_in, const int* in_sizes, int n_in,
                              void* d_out, int out_size)
{
    const float* coords = (const float*)d_in[0];
    const float* distsq = (const float*)d_in[1];
    const float* feats  = (const float*)d_in[2];
    const int*   nidx   = (const int*)  d_in[3];
    const float* W0 = (const float*)d_in[4];
    const float* b0 = (const float*)d_in[5];
    const float* W1 = (const float*)d_in[6];
    const float* b1 = (const float*)d_in[7];
    const float* W2 = (const float*)d_in[8];
    const float* b2 = (const float*)d_in[9];
    const float* W3 = (const float*)d_in[10];
    const float* b3 = (const float*)d_in[11];
    float* out = (float*)d_out;

    cov_kernel<<<Vn / VPB, 128>>>(coords, distsq, feats, nidx);

    cudaFuncSetAttribute(mlp_kernel,
                         cudaFuncAttributeMaxDynamicSharedMemorySize, MLP_SMEM);
    const int grid = (NTILES + TPB - 1) / TPB;   // 8334
    mlp_kernel<<<grid, 192, MLP_SMEM>>>(W0, b0, W1, b1, W2, b2, W3, b3, out);
}

// round 7
// speedup vs baseline: 1.1062x; 1.1062x over previous
#include <cuda_runtime.h>
#include <cuda_bf16.h>
#include <cstdint>
#include <cstddef>

// Problem constants
#define Vn 100000
#define Kn 64
#define Fn 16
#define VPB 8
#define EPSc 1e-4f
#define NTILES 100000        // 16-row MLP tiles

static const int R_ROWS = Vn * Fn;

// Scratch: cov rows [V*F, 9] (static device allocation — allowed)
__device__ float g_cov[(size_t)Vn * Fn * 9];

// ---------------------------------------------------------------------------
// Warp-MMA helpers (sm_80-era PTX: legal on plain sm_100)
// NOTE: mma is NON-volatile (pure reg dataflow) and ldsm has NO memory
// clobber — ptxas is free to software-pipeline loads over MMA bursts.
// ---------------------------------------------------------------------------
__device__ __forceinline__ uint32_t smem_u32(const void* p) {
    uint32_t a;
    asm("{ .reg .u64 t; cvta.to.shared.u64 t, %1; cvt.u32.u64 %0, t; }"
        : "=r"(a) : "l"(p));
    return a;
}

__device__ __forceinline__ void mma_bf16(float* d, const uint32_t* a,
                                         uint32_t b0, uint32_t b1) {
    asm("mma.sync.aligned.m16n8k16.row.col.f32.bf16.bf16.f32 "
        "{%0,%1,%2,%3}, {%4,%5,%6,%7}, {%8,%9}, {%0,%1,%2,%3};"
        : "+f"(d[0]), "+f"(d[1]), "+f"(d[2]), "+f"(d[3])
        : "r"(a[0]), "r"(a[1]), "r"(a[2]), "r"(a[3]), "r"(b0), "r"(b1));
}

__device__ __forceinline__ void ldsm4(uint32_t* r, uint32_t addr) {
    asm volatile("ldmatrix.sync.aligned.m8n8.x4.shared.b16 {%0,%1,%2,%3}, [%4];"
                 : "=r"(r[0]), "=r"(r[1]), "=r"(r[2]), "=r"(r[3])
                 : "r"(addr));
}

__device__ __forceinline__ void split2(float x0, float x1, uint32_t& h, uint32_t& l) {
    uint32_t hp;
    asm("cvt.rn.bf16x2.f32 %0, %1, %2;" : "=r"(hp) : "f"(x1), "f"(x0));
    const float h0 = __uint_as_float(hp << 16);
    const float h1 = __uint_as_float(hp & 0xFFFF0000u);
    const float l0 = x0 - h0;
    const float l1 = x1 - h1;
    uint32_t lp;
    asm("cvt.rn.bf16x2.f32 %0, %1, %2;" : "=r"(lp) : "f"(l1), "f"(l0));
    h = hp; l = lp;
}

// Branchless 5-op ELU: for t>=0 exp(min)=1 -> term 0, max picks t.
// For t<0: e^t-1 > t always, max picks e^t-1.
__device__ __forceinline__ float elu5(float t) {
    return fmaxf(t, __expf(fminf(t, 0.f)) - 1.0f);
}

// ---------------------------------------------------------------------------
// Kernel A: weighted neighbour covariance (unchanged)
// ---------------------------------------------------------------------------
__global__ void __launch_bounds__(128) cov_kernel(
    const float* __restrict__ coords,
    const float* __restrict__ distsq,
    const float* __restrict__ feats,
    const int*   __restrict__ nidx)
{
    __shared__ int   s_idx[VPB * Kn];
    __shared__ float s_ex [VPB * Kn];
    __shared__ float s_nbc[VPB * Kn * 3];

    const int v0 = blockIdx.x * VPB;

    for (int p = threadIdx.x; p < VPB * Kn; p += 128) {
        const int v  = v0 + (p >> 6);
        const int kk = p & 63;
        const int idx = nidx[v * Kn + kk];
        s_idx[p] = idx;
        s_ex[p]  = __expf(-10.0f * distsq[v * Kn + kk]);
        s_nbc[p * 3 + 0] = coords[idx * 3 + 0];
        s_nbc[p * 3 + 1] = coords[idx * 3 + 1];
        s_nbc[p * 3 + 2] = coords[idx * 3 + 2];
    }
    __syncthreads();

    const int lv = threadIdx.x >> 4;
    const int f  = threadIdx.x & 15;
    const int base = lv * Kn;

    float ws = 0.f, m0 = 0.f, m1 = 0.f, m2 = 0.f;
    float q00 = 0.f, q01 = 0.f, q02 = 0.f, q11 = 0.f, q12 = 0.f, q22 = 0.f;

    #pragma unroll 4
    for (int kk = 0; kk < Kn; kk++) {
        const int idx = s_idx[base + kk];
        const float w = __ldg(&feats[idx * Fn + f]) * s_ex[base + kk];
        const float x = s_nbc[(base + kk) * 3 + 0];
        const float y = s_nbc[(base + kk) * 3 + 1];
        const float z = s_nbc[(base + kk) * 3 + 2];
        ws += w;
        m0 = fmaf(w, x, m0); m1 = fmaf(w, y, m1); m2 = fmaf(w, z, m2);
        const float wx = w * x, wy = w * y, wz = w * z;
        q00 = fmaf(wx, x, q00); q01 = fmaf(wx, y, q01); q02 = fmaf(wx, z, q02);
        q11 = fmaf(wy, y, q11); q12 = fmaf(wy, z, q12); q22 = fmaf(wz, z, q22);
    }

    const float inv = 1.0f / (ws + EPSc);
    const float mu0 = m0 * inv, mu1 = m1 * inv, mu2 = m2 * inv;
    const float c0 = q00 * inv - mu0 * mu0;
    const float c1 = q01 * inv - mu0 * mu1;
    const float c2 = q02 * inv - mu0 * mu2;
    const float c4 = q11 * inv - mu1 * mu1;
    const float c5 = q12 * inv - mu1 * mu2;
    const float c8 = q22 * inv - mu2 * mu2;

    float* o = g_cov + ((size_t)(v0 + lv) * Fn + f) * 9;
    o[0] = c0; o[1] = c1; o[2] = c2;
    o[3] = c1; o[4] = c4; o[5] = c5;
    o[6] = c2; o[7] = c5; o[8] = c8;
}

// ---------------------------------------------------------------------------
// Kernel B v6: warp-MMA bf16-split MLP, 1 tile/warp, scheduler-friendly asm,
// bias folded into accumulator init, 5-op ELU.
// ---------------------------------------------------------------------------
#define PB   72
#define PB0  24
#define OFF_B1H 0
#define OFF_B1L 9216
#define OFF_B2H 18432
#define OFF_B2L 27648
#define OFF_B0H 36864
#define OFF_B0L 39936
#define OFF_B3H 43008
#define OFF_B3L 45312
#define OFF_BIAS 47616          /* 208 floats (b0,b1,b2,b3 padded to 16) */
#define OFF_AH  48448           /* 8 warps x 512 B */
#define OFF_AL  52544
#define MLP_SMEM 56640

__device__ __forceinline__ void put_hl(char* smc, int offH, int offL, int idx, float v) {
    const __nv_bfloat16 hb = __float2bfloat16_rn(v);
    const float lo = v - __bfloat162float(hb);
    ((__nv_bfloat16*)(smc + offH))[idx] = hb;
    ((__nv_bfloat16*)(smc + offL))[idx] = __float2bfloat16_rn(lo);
}

// Load this thread's bias fragment for a 64-wide layer: bf[2t],bf[2t+1]
__device__ __forceinline__ void bias_frag(const float* bias, int c, float* bf) {
    #pragma unroll
    for (int t = 0; t < 8; t++) {
        bf[2 * t]     = bias[8 * t + c];
        bf[2 * t + 1] = bias[8 * t + c + 1];
    }
}

__device__ __forceinline__ void init_d(float* d, const float* bf) {
    #pragma unroll
    for (int t = 0; t < 8; t++) {
        d[4 * t + 0] = bf[2 * t];
        d[4 * t + 1] = bf[2 * t + 1];
        d[4 * t + 2] = bf[2 * t];
        d[4 * t + 3] = bf[2 * t + 1];
    }
}

// One hidden-layer MMA pass: d[32] += (AH+AL) x B(hi/lo), K=64, N=64.
__device__ __forceinline__ void hidden_layer(
    float* d, const uint32_t* AH, const uint32_t* AL,
    uint32_t sb, int offH, int offL, int n, int koff)
{
    #pragma unroll
    for (int s = 0; s < 4; s++) {
        const uint32_t* ah = AH + 4 * s;
        const uint32_t* al = AL + 4 * s;
        #pragma unroll
        for (int ntp = 0; ntp < 4; ntp++) {
            const uint32_t ba = sb + ((n + ntp * 16) * PB + 16 * s + koff) * 2;
            uint32_t bh[4], bl[4];
            ldsm4(bh, ba + offH);
            ldsm4(bl, ba + offL);
            float* dp = d + ntp * 8;
            mma_bf16(dp, ah, bh[0], bh[1]);
            mma_bf16(dp, ah, bl[0], bl[1]);
            mma_bf16(dp, al, bh[0], bh[1]);
            mma_bf16(dp + 4, ah, bh[2], bh[3]);
            mma_bf16(dp + 4, ah, bl[2], bl[3]);
            mma_bf16(dp + 4, al, bh[2], bh[3]);
        }
    }
}

// Epilogue: ELU (bias already in accumulator) + repack into A frags.
__device__ __forceinline__ void epi_repack(float* d, uint32_t* AH, uint32_t* AL) {
    #pragma unroll
    for (int j = 0; j < 32; j++) d[j] = elu5(d[j]);
    #pragma unroll
    for (int s = 0; s < 4; s++) {
        split2(d[8 * s + 0], d[8 * s + 1], AH[4 * s + 0], AL[4 * s + 0]);
        split2(d[8 * s + 2], d[8 * s + 3], AH[4 * s + 1], AL[4 * s + 1]);
        split2(d[8 * s + 4], d[8 * s + 5], AH[4 * s + 2], AL[4 * s + 2]);
        split2(d[8 * s + 6], d[8 * s + 7], AH[4 * s + 3], AL[4 * s + 3]);
    }
}

__global__ void __launch_bounds__(256, 2) mlp_kernel(
    const float* __restrict__ W0, const float* __restrict__ b0,
    const float* __restrict__ W1, const float* __restrict__ b1,
    const float* __restrict__ W2, const float* __restrict__ b2,
    const float* __restrict__ W3, const float* __restrict__ b3,
    float* __restrict__ out)
{
    extern __shared__ char smc[];
    const uint32_t sb = smem_u32(smc);
    const int tid = threadIdx.x;
    const int lane = tid & 31;
    const int wid = tid >> 5;
    float* bias = (float*)(smc + OFF_BIAS);

    // ---- Stage weights (transposed, hi/lo split) + biases into SMEM ----
    for (int i = tid; i < 4096; i += 256) {
        const int n = i & 63, k = i >> 6;
        put_hl(smc, OFF_B1H, OFF_B1L, n * PB + k, W1[k * 64 + n]);
        put_hl(smc, OFF_B2H, OFF_B2L, n * PB + k, W2[k * 64 + n]);
    }
    for (int i = tid; i < 1024; i += 256) {
        const int n0 = i >> 4, k0 = i & 15;
        put_hl(smc, OFF_B0H, OFF_B0L, n0 * PB0 + k0, (k0 < 9) ? W0[k0 * 64 + n0] : 0.f);
        const int n3 = i >> 6, k3 = i & 63;
        put_hl(smc, OFF_B3H, OFF_B3L, n3 * PB + k3, (n3 < 9) ? W3[k3 * 9 + n3] : 0.f);
    }
    for (int i = tid; i < 208; i += 256) {
        float v = 0.f;
        if (i < 64) v = b0[i];
        else if (i < 128) v = b1[i - 64];
        else if (i < 192) v = b2[i - 128];
        else if (i < 201) v = b3[i - 192];
        bias[i] = v;
    }
    __syncthreads();

    // ---- Per-warp 16-row tile ----
    const int tile = blockIdx.x * 8 + wid;
    const size_t r0 = (size_t)tile * 16;

    // Stage input rows as bf16 hi/lo 16x16 tile (k padded with zeros)
    const uint32_t stoff = (uint32_t)wid * 512;
    if (lane < 16) {
        const float* src = g_cov + (r0 + lane) * 9;
        float x[10];
        #pragma unroll
        for (int q = 0; q < 9; q++) x[q] = src[q];
        x[9] = 0.f;
        uint32_t* ph = (uint32_t*)(smc + OFF_AH + stoff + lane * 32);
        uint32_t* pl = (uint32_t*)(smc + OFF_AL + stoff + lane * 32);
        #pragma unroll
        for (int cq = 0; cq < 5; cq++) {
            uint32_t h, l;
            split2(x[2 * cq], x[2 * cq + 1], h, l);
            ph[cq] = h; pl[cq] = l;
        }
        #pragma unroll
        for (int cq = 5; cq < 8; cq++) { ph[cq] = 0u; pl[cq] = 0u; }
    }
    __syncwarp();

    uint32_t A0h[4], A0l[4];
    {
        const uint32_t aaddr = sb + OFF_AH + stoff + (lane & 15) * 32 + ((lane >> 4) << 4);
        ldsm4(A0h, aaddr);
        ldsm4(A0l, aaddr + (OFF_AL - OFF_AH));
    }

    const int n    = (lane & 7) + ((lane >> 4) << 3);
    const int koff = ((lane >> 3) & 1) * 8;
    const int c    = (lane & 3) * 2;

    float bf[16];
    float d[32];

    // ---- Layer 0: K=16 (9 real), N=64; d init = b0 fragment ----
    bias_frag(bias + 0, c, bf);
    init_d(d, bf);
    #pragma unroll
    for (int ntp = 0; ntp < 4; ntp++) {
        const uint32_t ba = sb + ((n + ntp * 16) * PB0 + koff) * 2;
        uint32_t bh[4], bl[4];
        ldsm4(bh, ba + OFF_B0H);
        ldsm4(bl, ba + OFF_B0L);
        float* dp = d + ntp * 8;
        mma_bf16(dp, A0h, bh[0], bh[1]);
        mma_bf16(dp, A0h, bl[0], bl[1]);
        mma_bf16(dp, A0l, bh[0], bh[1]);
        mma_bf16(dp + 4, A0h, bh[2], bh[3]);
        mma_bf16(dp + 4, A0h, bl[2], bl[3]);
        mma_bf16(dp + 4, A0l, bh[2], bh[3]);
    }

    uint32_t AH[16], AL[16];

    // ---- Layer 1 ----
    epi_repack(d, AH, AL);
    bias_frag(bias + 64, c, bf);
    init_d(d, bf);
    hidden_layer(d, AH, AL, sb, OFF_B1H, OFF_B1L, n, koff);

    // ---- Layer 2 ----
    epi_repack(d, AH, AL);
    bias_frag(bias + 128, c, bf);
    init_d(d, bf);
    hidden_layer(d, AH, AL, sb, OFF_B2H, OFF_B2L, n, koff);

    // ---- Layer 3: K=64, N=16 (9 real); e init = b3 fragment ----
    epi_repack(d, AH, AL);

    float e[8];
    e[0] = bias[192 + c];       e[1] = bias[192 + c + 1];
    e[2] = e[0];                e[3] = e[1];
    e[4] = bias[200 + c];       e[5] = bias[200 + c + 1];   // zero-padded region
    e[6] = e[4];                e[7] = e[5];
    #pragma unroll
    for (int s = 0; s < 4; s++) {
        const uint32_t ba = sb + (n * PB + 16 * s + koff) * 2;
        uint32_t bh[4], bl[4];
        ldsm4(bh, ba + OFF_B3H);
        ldsm4(bl, ba + OFF_B3L);
        const uint32_t* ah = AH + 4 * s;
        const uint32_t* al = AL + 4 * s;
        mma_bf16(e, ah, bh[0], bh[1]);
        mma_bf16(e, ah, bl[0], bl[1]);
        mma_bf16(e, al, bh[0], bh[1]);
        mma_bf16(e + 4, ah, bh[2], bh[3]);
        mma_bf16(e + 4, ah, bl[2], bl[3]);
        mma_bf16(e + 4, al, bh[2], bh[3]);
    }

    // ---- Final accurate ELU + store (bias already in e) ----
    {
        const int row = lane >> 2;
        float* o0 = out + (r0 + row) * 9;
        float* o1 = out + (r0 + row + 8) * 9;
        float t;
        t = e[0]; o0[c]     = fmaxf(t, expm1f(fminf(t, 0.f)));
        t = e[1]; o0[c + 1] = fmaxf(t, expm1f(fminf(t, 0.f)));
        t = e[2]; o1[c]     = fmaxf(t, expm1f(fminf(t, 0.f)));
        t = e[3]; o1[c + 1] = fmaxf(t, expm1f(fminf(t, 0.f)));
        if ((lane & 3) == 0) {
            t = e[4]; o0[8] = fmaxf(t, expm1f(fminf(t, 0.f)));
            t = e[6]; o1[8] = fmaxf(t, expm1f(fminf(t, 0.f)));
        }
    }
}

// ---------------------------------------------------------------------------
// Launch
// ---------------------------------------------------------------------------
extern "C" void kernel_launch(void* const* d_in, const int* in_sizes, int n_in,
                              void* d_out, int out_size)
{
    const float* coords = (const float*)d_in[0];
    const float* distsq = (const float*)d_in[1];
    const float* feats  = (const float*)d_in[2];
    const int*   nidx   = (const int*)  d_in[3];
    const float* W0 = (const float*)d_in[4];
    const float* b0 = (const float*)d_in[5];
    const float* W1 = (const float*)d_in[6];
    const float* b1 = (const float*)d_in[7];
    const float* W2 = (const float*)d_in[8];
    const float* b2 = (const float*)d_in[9];
    const float* W3 = (const float*)d_in[10];
    const float* b3 = (const float*)d_in[11];
    float* out = (float*)d_out;

    cov_kernel<<<Vn / VPB, 128>>>(coords, distsq, feats, nidx);

    cudaFuncSetAttribute(mlp_kernel,
                         cudaFuncAttributeMaxDynamicSharedMemorySize, MLP_SMEM);
    mlp_kernel<<<NTILES / 8, 256, MLP_SMEM>>>(W0, b0, W1, b1, W2, b2, W3, b3, out);
}